// round 11
// baseline (speedup 1.0000x reference)
#include <cuda_runtime.h>
#include <cuda_fp16.h>
#include <cstdint>

// out[1024,4096] = tanh(x[1024,8192] @ scatter(W[8192,4096]) + bias)
// Dense legacy HMMA measured AT 512 MAC/cyc/SM floor (R6 = 100.3% of it).
// This round: 2:4 sparse mma.sp::ordered_metadata.m16n8k32 with W as the
// (compressed) A operand -> 2x MAC/instr. Rare >2-dense groups handled by a
// post-GEMM atomic fixup on pre-activation output, then a tanh pass.

#define D_DIM 8192
#define U_DIM 4096
#define B_ROWS 1024
#define FIX_CAP 8192

#define KC 64
#define N_ITER (D_DIM / KC)          // 128
#define A_PITCH 80                   // bytes per A_sp smem row (32 halves + pad)
#define B_PITCH 144                  // bytes per B smem row (64 halves + pad)
#define A_B 0
#define B_B (128 * A_PITCH)          // 10240
#define M_B (B_B + 256 * B_PITCH)    // 47104
#define STG_B (M_B + 1024)           // 48128
#define N_STAGES 4
#define SMEM_DYN (N_STAGES * STG_B)  // 192512

__device__ __half g_W[(size_t)U_DIM * D_DIM];          // dense Wt[u][d], 64 MB
__device__ __half g_X[(size_t)B_ROWS * D_DIM];         // fp16 x, 16 MB
__device__ __half g_Wsp[(size_t)U_DIM * (D_DIM / 2)];  // compressed, 32 MB
__device__ unsigned short g_meta16[(size_t)U_DIM * 512];  // per (u, k16) 4 nibbles
__device__ uint32_t g_metaw[(size_t)256 * 256 * 16];      // tile-ordered words
__device__ int   g_fcnt;
__device__ int2  g_fdu[FIX_CAP];
__device__ float g_fv[FIX_CAP];

// ---------------------------------------------------------------- helpers
__device__ __forceinline__ uint32_t smem_u32(const void* p) {
    uint32_t a;
    asm("{ .reg .u64 t; cvta.to.shared.u64 t, %1; cvt.u32.u64 %0, t; }"
        : "=r"(a) : "l"(p));
    return a;
}

__device__ __forceinline__ void mma_sp(float* c, const uint32_t* a, const uint32_t* b,
                                       uint32_t e) {
    asm volatile(
        "mma.sp::ordered_metadata.sync.aligned.m16n8k32.row.col.f32.f16.f16.f32 "
        "{%0,%1,%2,%3}, {%4,%5,%6,%7}, {%8,%9,%10,%11}, {%0,%1,%2,%3}, %12, 0x0;"
        : "+f"(c[0]), "+f"(c[1]), "+f"(c[2]), "+f"(c[3])
        : "r"(a[0]), "r"(a[1]), "r"(a[2]), "r"(a[3]),
          "r"(b[0]), "r"(b[1]), "r"(b[2]), "r"(b[3]), "r"(e));
}

#define LDMATRIX_X4(r0, r1, r2, r3, addr) \
    asm volatile("ldmatrix.sync.aligned.m8n8.x4.shared.b16 {%0,%1,%2,%3}, [%4];" \
                 : "=r"(r0), "=r"(r1), "=r"(r2), "=r"(r3) : "r"(addr))

#define CP_ASYNC16(sm, gp) \
    asm volatile("cp.async.cg.shared.global [%0], [%1], 16;" \
                 :: "r"(sm), "l"(gp) : "memory")
#define CP_COMMIT()  asm volatile("cp.async.commit_group;" ::: "memory")
#define CP_WAIT2()   asm volatile("cp.async.wait_group 2;" ::: "memory")

// ---------------------------------------------------------------- pre-passes
__global__ void conv_x_kernel(const float4* __restrict__ in, uint2* __restrict__ outp, int n4) {
    int i = blockIdx.x * blockDim.x + threadIdx.x;
    if (i < n4) {
        float4 v = in[i];
        __half2 lo = __floats2half2_rn(v.x, v.y);
        __half2 hi = __floats2half2_rn(v.z, v.w);
        outp[i] = make_uint2(*(uint32_t*)&lo, *(uint32_t*)&hi);
    }
}

__global__ void scatter_kernel(const int2* __restrict__ ind, const float* __restrict__ val,
                               __half* __restrict__ W, int nnz) {
    int i = blockIdx.x * blockDim.x + threadIdx.x;
    if (i < nnz) {
        int2 du = ind[i];
        atomicAdd(W + ((size_t)du.y * D_DIM + du.x), __float2half(val[i]));
    }
}

// 2:4 compression: one thread per (u, k32 block)
__global__ void compress_kernel(const __half* __restrict__ W, __half* __restrict__ Wsp,
                                unsigned short* __restrict__ meta16) {
    int idx = blockIdx.x * blockDim.x + threadIdx.x;
    if (idx >= U_DIM * 256) return;
    int u = idx >> 8, kb = idx & 255;
    const __half* src = W + (size_t)u * D_DIM + kb * 32;
    __half vals[32];
    *(uint4*)(vals)      = *(const uint4*)(src);
    *(uint4*)(vals + 8)  = *(const uint4*)(src + 8);
    *(uint4*)(vals + 16) = *(const uint4*)(src + 16);
    *(uint4*)(vals + 24) = *(const uint4*)(src + 24);
    __half out[16];
    unsigned short m16[2] = {0, 0};
    for (int gl = 0; gl < 8; gl++) {
        int ids[4]; int n = 0;
#pragma unroll
        for (int i = 0; i < 4; i++)
            if (__half_as_ushort(vals[gl * 4 + i]) & 0x7fff) ids[n++] = i;
        int i0 = 0, i1 = 1; __half v0, v1;
        const __half hz = __ushort_as_half(0);
        if (n == 0)       { v0 = hz; v1 = hz; }
        else if (n == 1)  {
            if (ids[0] == 0) { v0 = vals[gl * 4]; v1 = hz; }
            else { i1 = ids[0]; v0 = hz; v1 = vals[gl * 4 + i1]; }
        } else {
            i0 = ids[0]; i1 = ids[1];
            v0 = vals[gl * 4 + i0]; v1 = vals[gl * 4 + i1];
            for (int t = 2; t < n; t++) {           // overflow -> fixup list
                int pos = atomicAdd(&g_fcnt, 1);
                if (pos < FIX_CAP) {
                    g_fdu[pos] = make_int2(kb * 32 + gl * 4 + ids[t], u);
                    g_fv[pos]  = __half2float(vals[gl * 4 + ids[t]]);
                }
            }
        }
        out[gl * 2] = v0; out[gl * 2 + 1] = v1;
        m16[gl >> 2] |= (unsigned short)((i0 | (i1 << 2)) << ((gl & 3) * 4));
    }
    __half* dst = Wsp + (size_t)u * (D_DIM / 2) + kb * 16;
    *(uint4*)(dst)     = *(uint4*)(out);
    *(uint4*)(dst + 8) = *(uint4*)(out + 8);
    meta16[u * 512 + kb * 2]     = m16[0];
    meta16[u * 512 + kb * 2 + 1] = m16[1];
}

// assemble per-thread metadata words: word(q,h) = {row q: k16 h} | {row q+8}<<16
__global__ void meta_asm_kernel(const unsigned short* __restrict__ meta16,
                                uint32_t* __restrict__ metaw) {
    int idx = blockIdx.x * blockDim.x + threadIdx.x;
    if (idx >= 256 * 256 * 16) return;
    int j = idx & 15, k32b = (idx >> 4) & 255, ub = idx >> 12;
    int q = j >> 1, h = j & 1;
    uint32_t lo = meta16[(ub * 16 + q) * 512 + k32b * 2 + h];
    uint32_t hi = meta16[(ub * 16 + q + 8) * 512 + k32b * 2 + h];
    metaw[idx] = lo | (hi << 16);
}

// ---------------------------------------------------------------- sp-GEMM
// z[u][m] tiles: A = Wsp (sparse, u x K), B = x (m cols, K-major). Writes
// pre-activation (bias added, no tanh) to out[m][u].
__global__ void __launch_bounds__(256, 1)
spgemm_kernel(const __half* __restrict__ gA,    // g_Wsp
              const uint32_t* __restrict__ gM,  // g_metaw
              const __half* __restrict__ gB,    // g_X
              const float* __restrict__ bias,
              float* __restrict__ out) {
    extern __shared__ char smem[];
    uint32_t sbase = smem_u32(smem);

    const int tid  = threadIdx.x;
    const int lane = tid & 31;
    const int wid  = tid >> 5;
    const int wm   = wid >> 2;        // u-warp 0..1 (64 rows)
    const int wn   = wid & 3;         // m-warp 0..3 (64 cols)
    const int mt = blockIdx.x & 3;
    const int ut = blockIdx.x >> 2;
    const int u0 = ut * 128, mm0 = mt * 256;

    const int am = (((lane >> 3) & 1) << 3) + (lane & 7);
    const int ak = (lane >> 4) << 3;          // halves
    const int bn = ((lane >> 4) << 3) + (lane & 7);
    const int bk = (((lane >> 3) & 1)) << 3;  // halves
    const int j4 = (2 * (lane >> 2) + (lane & 1)) * 4;

    uint32_t aoff[4], boff[4], moff[4];
#pragma unroll
    for (int f = 0; f < 4; f++) {
        aoff[f] = (uint32_t)(A_B + (wm * 64 + f * 16 + am) * A_PITCH + ak * 2);
        moff[f] = (uint32_t)(M_B + (wm * 4 + f) * 128 + j4);
    }
#pragma unroll
    for (int p = 0; p < 4; p++)
        boff[p] = (uint32_t)(B_B + (wn * 64 + p * 16 + bn) * B_PITCH + bk * 2);

    float acc[4][8][4];
#pragma unroll
    for (int f = 0; f < 4; f++)
#pragma unroll
        for (int bf = 0; bf < 8; bf++)
#pragma unroll
            for (int k = 0; k < 4; k++) acc[f][bf][k] = 0.f;

    auto stage_load = [&](int s, int kt) {
        uint32_t st = sbase + (uint32_t)(s * STG_B);
#pragma unroll
        for (int i = 0; i < 2; i++) {   // A_sp: 512 chunks
            int ch = tid + i * 256, row = ch >> 2, c = ch & 3;
            CP_ASYNC16(st + A_B + row * A_PITCH + c * 16,
                       gA + (size_t)(u0 + row) * (D_DIM / 2) + kt * 32 + c * 8);
        }
#pragma unroll
        for (int i = 0; i < 8; i++) {   // B: 2048 chunks
            int ch = tid + i * 256, row = ch >> 3, c = ch & 7;
            CP_ASYNC16(st + B_B + row * B_PITCH + c * 16,
                       gB + (size_t)(mm0 + row) * D_DIM + kt * 64 + c * 8);
        }
        if (tid < 64) {                 // meta: 64 chunks
            int ub = tid >> 3, r = tid & 7, ks = r >> 2, q4 = r & 3;
            CP_ASYNC16(st + M_B + (ub * 2 + ks) * 64 + q4 * 16,
                       gM + ((size_t)((u0 >> 4) + ub) * 256 + (kt * 2 + ks)) * 16 + q4 * 4);
        }
    };

#pragma unroll
    for (int s = 0; s < 3; s++) { stage_load(s, s); CP_COMMIT(); }

    for (int it = 0; it < N_ITER; it++) {
        const int s = it & (N_STAGES - 1);
        CP_WAIT2();
        __syncthreads();
        if (it + 3 < N_ITER) stage_load((it + 3) & (N_STAGES - 1), it + 3);
        CP_COMMIT();

        const uint32_t stg = sbase + (uint32_t)(s * STG_B);
#pragma unroll
        for (int ks = 0; ks < 2; ks++) {
            uint32_t a[4][4], e[4], rb[4][8];
#pragma unroll
            for (int f = 0; f < 4; f++) {
                LDMATRIX_X4(a[f][0], a[f][1], a[f][2], a[f][3], stg + aoff[f] + ks * 32);
                asm volatile("ld.shared.b32 %0, [%1];" : "=r"(e[f])
                             : "r"(stg + moff[f] + ks * 64));
            }
#pragma unroll
            for (int p = 0; p < 4; p++) {
                LDMATRIX_X4(rb[p][0], rb[p][1], rb[p][2], rb[p][3],
                            stg + boff[p] + ks * 64);
                LDMATRIX_X4(rb[p][4], rb[p][5], rb[p][6], rb[p][7],
                            stg + boff[p] + ks * 64 + 32);
            }
#pragma unroll
            for (int bf = 0; bf < 8; bf++) {
                const int p = bf >> 1, jj = (bf & 1) << 1;
                uint32_t bb[4] = {rb[p][jj], rb[p][jj + 1], rb[p][4 + jj], rb[p][5 + jj]};
#pragma unroll
                for (int f = 0; f < 4; f++) mma_sp(acc[f][bf], a[f], bb, e[f]);
            }
        }
    }

    // epilogue: z = acc + bias[u], transposed store to out[m][u] (no tanh yet)
#pragma unroll
    for (int f = 0; f < 4; f++) {
        const int uu = u0 + wm * 64 + f * 16 + (lane >> 2);
        const float b0 = __ldg(bias + uu), b1 = __ldg(bias + uu + 8);
#pragma unroll
        for (int bf = 0; bf < 8; bf++) {
            const int mm = mm0 + wn * 64 + bf * 8 + 2 * (lane & 3);
            out[(size_t)mm * U_DIM + uu]           = acc[f][bf][0] + b0;
            out[(size_t)(mm + 1) * U_DIM + uu]     = acc[f][bf][1] + b0;
            out[(size_t)mm * U_DIM + uu + 8]       = acc[f][bf][2] + b1;
            out[(size_t)(mm + 1) * U_DIM + uu + 8] = acc[f][bf][3] + b1;
        }
    }
}

// ---------------------------------------------------------------- fixup + tanh
__global__ void fixup_kernel(float* __restrict__ out) {
    int idx = blockIdx.x * blockDim.x + threadIdx.x;
    int e = idx >> 10, m = idx & 1023;
    if (e >= g_fcnt || e >= FIX_CAP) return;
    int2 du = g_fdu[e];
    float xv = __half2float(g_X[(size_t)m * D_DIM + du.x]);
    atomicAdd(out + (size_t)m * U_DIM + du.y, xv * g_fv[e]);
}

__global__ void tanh_kernel(float4* __restrict__ out, int n4) {
    int i = blockIdx.x * blockDim.x + threadIdx.x;
    if (i < n4) {
        float4 v = out[i];
        v.x = tanhf(v.x); v.y = tanhf(v.y); v.z = tanhf(v.z); v.w = tanhf(v.w);
        out[i] = v;
    }
}

// ---------------------------------------------------------------- host side
extern "C" void kernel_launch(void* const* d_in, const int* in_sizes, int n_in,
                              void* d_out, int out_size) {
    const float* x    = (const float*)d_in[0];
    const float* kv   = (const float*)d_in[1];
    const float* bias = (const float*)d_in[2];
    const int*   ind  = (const int*)d_in[3];
    float* out = (float*)d_out;
    int nnz = in_sizes[1];

    void *wptr, *xptr, *wsp, *m16, *mw, *cnt;
    cudaGetSymbolAddress(&wptr, g_W);
    cudaGetSymbolAddress(&xptr, g_X);
    cudaGetSymbolAddress(&wsp, g_Wsp);
    cudaGetSymbolAddress(&m16, g_meta16);
    cudaGetSymbolAddress(&mw, g_metaw);
    cudaGetSymbolAddress(&cnt, g_fcnt);

    cudaFuncSetAttribute(spgemm_kernel,
                         cudaFuncAttributeMaxDynamicSharedMemorySize, SMEM_DYN);

    cudaMemsetAsync(wptr, 0, (size_t)U_DIM * D_DIM * sizeof(__half));
    cudaMemsetAsync(cnt, 0, 4);

    int n4 = B_ROWS * D_DIM / 4;
    conv_x_kernel<<<(n4 + 255) / 256, 256>>>((const float4*)x, (uint2*)xptr, n4);

    scatter_kernel<<<(nnz + 255) / 256, 256>>>((const int2*)ind, kv, (__half*)wptr, nnz);

    compress_kernel<<<(U_DIM * 256) / 256, 256>>>((const __half*)wptr, (__half*)wsp,
                                                  (unsigned short*)m16);
    meta_asm_kernel<<<(256 * 256 * 16) / 256, 256>>>((const unsigned short*)m16,
                                                     (uint32_t*)mw);

    spgemm_kernel<<<(U_DIM / 128) * (B_ROWS / 256), 256, SMEM_DYN>>>(
        (const __half*)wsp, (const uint32_t*)mw, (const __half*)xptr, bias, out);

    fixup_kernel<<<(FIX_CAP * 1024) / 256, 256>>>(out);

    int no4 = B_ROWS * U_DIM / 4;
    tanh_kernel<<<(no4 + 255) / 256, 256>>>((float4*)out, no4);
}

// round 12
// speedup vs baseline: 1.0114x; 1.0114x over previous
#include <cuda_runtime.h>
#include <cuda_fp16.h>
#include <cstdint>

// out[1024,4096] = tanh(x[1024,8192] @ scatter(W[8192,4096]) + bias)
// 2:4 sparse mma.sp::ordered_metadata path (validated correct in R11).
// R12: (a) launch order puts spgemm at position 6 so ncu -s5 -c1 captures it,
// (b) tile order flipped so consecutive CTAs share the x (B) block in L2.

#define D_DIM 8192
#define U_DIM 4096
#define B_ROWS 1024
#define FIX_CAP 8192

#define KC 64
#define N_ITER (D_DIM / KC)          // 128
#define A_PITCH 80                   // bytes per A_sp smem row (32 halves + pad)
#define B_PITCH 144                  // bytes per B smem row (64 halves + pad)
#define A_B 0
#define B_B (128 * A_PITCH)          // 10240
#define M_B (B_B + 256 * B_PITCH)    // 47104
#define STG_B (M_B + 1024)           // 48128
#define N_STAGES 4
#define SMEM_DYN (N_STAGES * STG_B)  // 192512

__device__ __half g_W[(size_t)U_DIM * D_DIM];          // dense Wt[u][d], 64 MB
__device__ __half g_X[(size_t)B_ROWS * D_DIM];         // fp16 x, 16 MB
__device__ __half g_Wsp[(size_t)U_DIM * (D_DIM / 2)];  // compressed, 32 MB
__device__ unsigned short g_meta16[(size_t)U_DIM * 512];  // per (u, k16) 4 nibbles
__device__ uint32_t g_metaw[(size_t)256 * 256 * 16];      // tile-ordered words
__device__ int   g_fcnt;
__device__ int2  g_fdu[FIX_CAP];
__device__ float g_fv[FIX_CAP];

// ---------------------------------------------------------------- helpers
__device__ __forceinline__ uint32_t smem_u32(const void* p) {
    uint32_t a;
    asm("{ .reg .u64 t; cvta.to.shared.u64 t, %1; cvt.u32.u64 %0, t; }"
        : "=r"(a) : "l"(p));
    return a;
}

__device__ __forceinline__ void mma_sp(float* c, const uint32_t* a, const uint32_t* b,
                                       uint32_t e) {
    asm volatile(
        "mma.sp::ordered_metadata.sync.aligned.m16n8k32.row.col.f32.f16.f16.f32 "
        "{%0,%1,%2,%3}, {%4,%5,%6,%7}, {%8,%9,%10,%11}, {%0,%1,%2,%3}, %12, 0x0;"
        : "+f"(c[0]), "+f"(c[1]), "+f"(c[2]), "+f"(c[3])
        : "r"(a[0]), "r"(a[1]), "r"(a[2]), "r"(a[3]),
          "r"(b[0]), "r"(b[1]), "r"(b[2]), "r"(b[3]), "r"(e));
}

#define LDMATRIX_X4(r0, r1, r2, r3, addr) \
    asm volatile("ldmatrix.sync.aligned.m8n8.x4.shared.b16 {%0,%1,%2,%3}, [%4];" \
                 : "=r"(r0), "=r"(r1), "=r"(r2), "=r"(r3) : "r"(addr))

#define CP_ASYNC16(sm, gp) \
    asm volatile("cp.async.cg.shared.global [%0], [%1], 16;" \
                 :: "r"(sm), "l"(gp) : "memory")
#define CP_COMMIT()  asm volatile("cp.async.commit_group;" ::: "memory")
#define CP_WAIT2()   asm volatile("cp.async.wait_group 2;" ::: "memory")

// ---------------------------------------------------------------- pre-passes
__global__ void conv_x_kernel(const float4* __restrict__ in, uint2* __restrict__ outp, int n4) {
    int i = blockIdx.x * blockDim.x + threadIdx.x;
    if (i == 0) g_fcnt = 0;                 // replaces a separate memset launch
    if (i < n4) {
        float4 v = in[i];
        __half2 lo = __floats2half2_rn(v.x, v.y);
        __half2 hi = __floats2half2_rn(v.z, v.w);
        outp[i] = make_uint2(*(uint32_t*)&lo, *(uint32_t*)&hi);
    }
}

__global__ void scatter_kernel(const int2* __restrict__ ind, const float* __restrict__ val,
                               __half* __restrict__ W, int nnz) {
    int i = blockIdx.x * blockDim.x + threadIdx.x;
    if (i < nnz) {
        int2 du = ind[i];
        atomicAdd(W + ((size_t)du.y * D_DIM + du.x), __float2half(val[i]));
    }
}

// 2:4 compression: one thread per (u, k32 block)
__global__ void compress_kernel(const __half* __restrict__ W, __half* __restrict__ Wsp,
                                unsigned short* __restrict__ meta16) {
    int idx = blockIdx.x * blockDim.x + threadIdx.x;
    if (idx >= U_DIM * 256) return;
    int u = idx >> 8, kb = idx & 255;
    const __half* src = W + (size_t)u * D_DIM + kb * 32;
    __half vals[32];
    *(uint4*)(vals)      = *(const uint4*)(src);
    *(uint4*)(vals + 8)  = *(const uint4*)(src + 8);
    *(uint4*)(vals + 16) = *(const uint4*)(src + 16);
    *(uint4*)(vals + 24) = *(const uint4*)(src + 24);
    __half out[16];
    unsigned short m16[2] = {0, 0};
    for (int gl = 0; gl < 8; gl++) {
        int ids[4]; int n = 0;
#pragma unroll
        for (int i = 0; i < 4; i++)
            if (__half_as_ushort(vals[gl * 4 + i]) & 0x7fff) ids[n++] = i;
        int i0 = 0, i1 = 1; __half v0, v1;
        const __half hz = __ushort_as_half(0);
        if (n == 0)       { v0 = hz; v1 = hz; }
        else if (n == 1)  {
            if (ids[0] == 0) { v0 = vals[gl * 4]; v1 = hz; }
            else { i1 = ids[0]; v0 = hz; v1 = vals[gl * 4 + i1]; }
        } else {
            i0 = ids[0]; i1 = ids[1];
            v0 = vals[gl * 4 + i0]; v1 = vals[gl * 4 + i1];
            for (int t = 2; t < n; t++) {           // overflow -> fixup list
                int pos = atomicAdd(&g_fcnt, 1);
                if (pos < FIX_CAP) {
                    g_fdu[pos] = make_int2(kb * 32 + gl * 4 + ids[t], u);
                    g_fv[pos]  = __half2float(vals[gl * 4 + ids[t]]);
                }
            }
        }
        out[gl * 2] = v0; out[gl * 2 + 1] = v1;
        m16[gl >> 2] |= (unsigned short)((i0 | (i1 << 2)) << ((gl & 3) * 4));
    }
    __half* dst = Wsp + (size_t)u * (D_DIM / 2) + kb * 16;
    *(uint4*)(dst)     = *(uint4*)(out);
    *(uint4*)(dst + 8) = *(uint4*)(out + 8);
    meta16[u * 512 + kb * 2]     = m16[0];
    meta16[u * 512 + kb * 2 + 1] = m16[1];
}

// assemble per-thread metadata words: word(q,h) = {row q: k16 h} | {row q+8}<<16
__global__ void meta_asm_kernel(const unsigned short* __restrict__ meta16,
                                uint32_t* __restrict__ metaw) {
    int idx = blockIdx.x * blockDim.x + threadIdx.x;
    if (idx >= 256 * 256 * 16) return;
    int j = idx & 15, k32b = (idx >> 4) & 255, ub = idx >> 12;
    int q = j >> 1, h = j & 1;
    uint32_t lo = meta16[(ub * 16 + q) * 512 + k32b * 2 + h];
    uint32_t hi = meta16[(ub * 16 + q + 8) * 512 + k32b * 2 + h];
    metaw[idx] = lo | (hi << 16);
}

// ---------------------------------------------------------------- sp-GEMM
__global__ void __launch_bounds__(256, 1)
spgemm_kernel(const __half* __restrict__ gA,    // g_Wsp
              const uint32_t* __restrict__ gM,  // g_metaw
              const __half* __restrict__ gB,    // g_X
              const float* __restrict__ bias,
              float* __restrict__ out) {
    extern __shared__ char smem[];
    uint32_t sbase = smem_u32(smem);

    const int tid  = threadIdx.x;
    const int lane = tid & 31;
    const int wid  = tid >> 5;
    const int wm   = wid >> 2;        // u-warp 0..1 (64 rows)
    const int wn   = wid & 3;         // m-warp 0..3 (64 cols)
    const int ut = blockIdx.x & 31;   // consecutive bids share the x (B) block
    const int mt = blockIdx.x >> 5;
    const int u0 = ut * 128, mm0 = mt * 256;

    const int am = (((lane >> 3) & 1) << 3) + (lane & 7);
    const int ak = (lane >> 4) << 3;          // halves
    const int bn = ((lane >> 4) << 3) + (lane & 7);
    const int bk = (((lane >> 3) & 1)) << 3;  // halves
    const int j4 = (2 * (lane >> 2) + (lane & 1)) * 4;

    uint32_t aoff[4], boff[4], moff[4];
#pragma unroll
    for (int f = 0; f < 4; f++) {
        aoff[f] = (uint32_t)(A_B + (wm * 64 + f * 16 + am) * A_PITCH + ak * 2);
        moff[f] = (uint32_t)(M_B + (wm * 4 + f) * 128 + j4);
    }
#pragma unroll
    for (int p = 0; p < 4; p++)
        boff[p] = (uint32_t)(B_B + (wn * 64 + p * 16 + bn) * B_PITCH + bk * 2);

    float acc[4][8][4];
#pragma unroll
    for (int f = 0; f < 4; f++)
#pragma unroll
        for (int bf = 0; bf < 8; bf++)
#pragma unroll
            for (int k = 0; k < 4; k++) acc[f][bf][k] = 0.f;

    auto stage_load = [&](int s, int kt) {
        uint32_t st = sbase + (uint32_t)(s * STG_B);
#pragma unroll
        for (int i = 0; i < 2; i++) {   // A_sp: 512 chunks
            int ch = tid + i * 256, row = ch >> 2, c = ch & 3;
            CP_ASYNC16(st + A_B + row * A_PITCH + c * 16,
                       gA + (size_t)(u0 + row) * (D_DIM / 2) + kt * 32 + c * 8);
        }
#pragma unroll
        for (int i = 0; i < 8; i++) {   // B: 2048 chunks
            int ch = tid + i * 256, row = ch >> 3, c = ch & 7;
            CP_ASYNC16(st + B_B + row * B_PITCH + c * 16,
                       gB + (size_t)(mm0 + row) * D_DIM + kt * 64 + c * 8);
        }
        if (tid < 64) {                 // meta: 64 chunks
            int ub = tid >> 3, r = tid & 7, ks = r >> 2, q4 = r & 3;
            CP_ASYNC16(st + M_B + (ub * 2 + ks) * 64 + q4 * 16,
                       gM + ((size_t)((u0 >> 4) + ub) * 256 + (kt * 2 + ks)) * 16 + q4 * 4);
        }
    };

#pragma unroll
    for (int s = 0; s < 3; s++) { stage_load(s, s); CP_COMMIT(); }

    for (int it = 0; it < N_ITER; it++) {
        const int s = it & (N_STAGES - 1);
        CP_WAIT2();
        __syncthreads();
        if (it + 3 < N_ITER) stage_load((it + 3) & (N_STAGES - 1), it + 3);
        CP_COMMIT();

        const uint32_t stg = sbase + (uint32_t)(s * STG_B);
#pragma unroll
        for (int ks = 0; ks < 2; ks++) {
            uint32_t a[4][4], e[4], rb[4][8];
#pragma unroll
            for (int f = 0; f < 4; f++) {
                LDMATRIX_X4(a[f][0], a[f][1], a[f][2], a[f][3], stg + aoff[f] + ks * 32);
                asm volatile("ld.shared.b32 %0, [%1];" : "=r"(e[f])
                             : "r"(stg + moff[f] + ks * 64));
            }
#pragma unroll
            for (int p = 0; p < 4; p++) {
                LDMATRIX_X4(rb[p][0], rb[p][1], rb[p][2], rb[p][3],
                            stg + boff[p] + ks * 64);
                LDMATRIX_X4(rb[p][4], rb[p][5], rb[p][6], rb[p][7],
                            stg + boff[p] + ks * 64 + 32);
            }
#pragma unroll
            for (int bf = 0; bf < 8; bf++) {
                const int p = bf >> 1, jj = (bf & 1) << 1;
                uint32_t bb[4] = {rb[p][jj], rb[p][jj + 1], rb[p][4 + jj], rb[p][5 + jj]};
#pragma unroll
                for (int f = 0; f < 4; f++) mma_sp(acc[f][bf], a[f], bb, e[f]);
            }
        }
    }

    // epilogue: z = acc + bias[u], transposed store to out[m][u] (no tanh yet)
#pragma unroll
    for (int f = 0; f < 4; f++) {
        const int uu = u0 + wm * 64 + f * 16 + (lane >> 2);
        const float b0 = __ldg(bias + uu), b1 = __ldg(bias + uu + 8);
#pragma unroll
        for (int bf = 0; bf < 8; bf++) {
            const int mm = mm0 + wn * 64 + bf * 8 + 2 * (lane & 3);
            out[(size_t)mm * U_DIM + uu]           = acc[f][bf][0] + b0;
            out[(size_t)(mm + 1) * U_DIM + uu]     = acc[f][bf][1] + b0;
            out[(size_t)mm * U_DIM + uu + 8]       = acc[f][bf][2] + b1;
            out[(size_t)(mm + 1) * U_DIM + uu + 8] = acc[f][bf][3] + b1;
        }
    }
}

// ---------------------------------------------------------------- fixup + tanh
__global__ void fixup_kernel(float* __restrict__ out) {
    int idx = blockIdx.x * blockDim.x + threadIdx.x;
    int e = idx >> 10, m = idx & 1023;
    if (e >= g_fcnt || e >= FIX_CAP) return;
    int2 du = g_fdu[e];
    float xv = __half2float(g_X[(size_t)m * D_DIM + du.x]);
    atomicAdd(out + (size_t)m * U_DIM + du.y, xv * g_fv[e]);
}

__global__ void tanh_kernel(float4* __restrict__ out, int n4) {
    int i = blockIdx.x * blockDim.x + threadIdx.x;
    if (i < n4) {
        float4 v = out[i];
        v.x = tanhf(v.x); v.y = tanhf(v.y); v.z = tanhf(v.z); v.w = tanhf(v.w);
        out[i] = v;
    }
}

// ---------------------------------------------------------------- host side
extern "C" void kernel_launch(void* const* d_in, const int* in_sizes, int n_in,
                              void* d_out, int out_size) {
    const float* x    = (const float*)d_in[0];
    const float* kv   = (const float*)d_in[1];
    const float* bias = (const float*)d_in[2];
    const int*   ind  = (const int*)d_in[3];
    float* out = (float*)d_out;
    int nnz = in_sizes[1];

    void *wptr, *xptr, *wsp, *m16, *mw;
    cudaGetSymbolAddress(&wptr, g_W);
    cudaGetSymbolAddress(&xptr, g_X);
    cudaGetSymbolAddress(&wsp, g_Wsp);
    cudaGetSymbolAddress(&m16, g_meta16);
    cudaGetSymbolAddress(&mw, g_metaw);

    cudaFuncSetAttribute(spgemm_kernel,
                         cudaFuncAttributeMaxDynamicSharedMemorySize, SMEM_DYN);

    // Launch order (ncu -s 5 -c 1 captures #6 = spgemm):
    // 1 memset W, 2 conv_x (zeroes g_fcnt), 3 scatter, 4 compress, 5 meta, 6 spgemm
    cudaMemsetAsync(wptr, 0, (size_t)U_DIM * D_DIM * sizeof(__half));

    int n4 = B_ROWS * D_DIM / 4;
    conv_x_kernel<<<(n4 + 255) / 256, 256>>>((const float4*)x, (uint2*)xptr, n4);

    scatter_kernel<<<(nnz + 255) / 256, 256>>>((const int2*)ind, kv, (__half*)wptr, nnz);

    compress_kernel<<<(U_DIM * 256) / 256, 256>>>((const __half*)wptr, (__half*)wsp,
                                                  (unsigned short*)m16);
    meta_asm_kernel<<<(256 * 256 * 16) / 256, 256>>>((const unsigned short*)m16,
                                                     (uint32_t*)mw);

    spgemm_kernel<<<(U_DIM / 128) * (B_ROWS / 256), 256, SMEM_DYN>>>(
        (const __half*)wsp, (const uint32_t*)mw, (const __half*)xptr, bias, out);

    fixup_kernel<<<(FIX_CAP * 1024) / 256, 256>>>(out);

    int no4 = B_ROWS * U_DIM / 4;
    tanh_kernel<<<(no4 + 255) / 256, 256>>>((float4*)out, no4);
}

// round 13
// speedup vs baseline: 1.1669x; 1.1538x over previous
#include <cuda_runtime.h>
#include <cuda_fp16.h>
#include <cstdint>

// out[1024,4096] = tanh(x[1024,8192] @ scatter(W[8192,4096]) + bias)
// sm_100 base target (no tcgen05). Converged model: ALL mma.sync flavors
// (tf32 / fp16-f32acc / fp16-f16acc / mma.sp) = 512 MAC/cyc/SM. Dense R6
// GEMM measured at 100.3% of that floor (251.4us) -> GEMM is final.
// This round: R6 GEMM verbatim + fused memset(W)+conv(x) prep pass.

#define D_DIM 8192
#define U_DIM 4096
#define B_ROWS 1024

#define MT 128
#define NT 256
#define KC 64
#define PITCH 72                           // halves per smem row (pad 64->72)
#define A_ST (MT * PITCH)                  // 9216 halves
#define B_ST (NT * PITCH)                  // 18432 halves
#define STG_H (A_ST + B_ST)                // 27648 halves
#define N_STAGES 4
#define SMEM_DYN (N_STAGES * STG_H * 2)    // 221184 B
#define N_ITER (D_DIM / KC)                // 128

#define NW4 ((int)((size_t)U_DIM * D_DIM * 2 / 16))   // uint4 chunks of W: 4194304
#define NX4 (B_ROWS * D_DIM / 4)                      // float4 chunks of x: 2097152

__device__ __half g_W[(size_t)U_DIM * D_DIM];  // Wt[u][d], 64 MB
__device__ __half g_X[(size_t)B_ROWS * D_DIM]; // fp16 x, 16 MB

// ---------------------------------------------------------------- helpers
__device__ __forceinline__ uint32_t smem_u32(const void* p) {
    uint32_t a;
    asm("{ .reg .u64 t; cvta.to.shared.u64 t, %1; cvt.u32.u64 %0, t; }"
        : "=r"(a) : "l"(p));
    return a;
}

__device__ __forceinline__ void mma_f16(float* c, const uint32_t* a, const uint32_t* b) {
    asm volatile(
        "mma.sync.aligned.m16n8k16.row.col.f32.f16.f16.f32 "
        "{%0,%1,%2,%3}, {%4,%5,%6,%7}, {%8,%9}, {%0,%1,%2,%3};"
        : "+f"(c[0]), "+f"(c[1]), "+f"(c[2]), "+f"(c[3])
        : "r"(a[0]), "r"(a[1]), "r"(a[2]), "r"(a[3]), "r"(b[0]), "r"(b[1]));
}

#define CP_ASYNC16(sm, gp) \
    asm volatile("cp.async.cg.shared.global [%0], [%1], 16;" \
                 :: "r"(sm), "l"(gp) : "memory")
#define CP_COMMIT()  asm volatile("cp.async.commit_group;" ::: "memory")
#define CP_WAIT2()   asm volatile("cp.async.wait_group 2;" ::: "memory")

// ---------------------------------------------------------------- fused prep
// blocks [0, NW4/256): zero W.  blocks beyond: convert x to fp16.
__global__ void prep_kernel(const float4* __restrict__ xin, uint2* __restrict__ xout,
                            uint4* __restrict__ w) {
    int i = blockIdx.x * blockDim.x + threadIdx.x;
    if (i < NW4) {
        w[i] = make_uint4(0u, 0u, 0u, 0u);
    } else {
        int j = i - NW4;
        if (j < NX4) {
            float4 v = xin[j];
            __half2 lo = __floats2half2_rn(v.x, v.y);
            __half2 hi = __floats2half2_rn(v.z, v.w);
            xout[j] = make_uint2(*(uint32_t*)&lo, *(uint32_t*)&hi);
        }
    }
}

__global__ void scatter_kernel(const int2* __restrict__ ind, const float* __restrict__ val,
                               __half* __restrict__ W, int nnz) {
    int i = blockIdx.x * blockDim.x + threadIdx.x;
    if (i < nnz) {
        int2 du = ind[i];  // .x = d (row of dense W), .y = u (col)
        atomicAdd(W + ((size_t)du.y * D_DIM + du.x), __float2half(val[i]));
    }
}

// ---------------------------------------------------------------- GEMM (R6 verbatim, measured 251.4us)
__global__ void __launch_bounds__(256, 1)
sparse_gemm_kernel(const __half* __restrict__ gA,   // g_X [1024][8192]
                   const __half* __restrict__ gB,   // g_W [4096][8192]
                   const float* __restrict__ bias,
                   float* __restrict__ out) {
    extern __shared__ __half smem[];
    uint32_t sbase = smem_u32(smem);

    const int tid  = threadIdx.x;
    const int lane = tid & 31;
    const int wid  = tid >> 5;
    const int wm   = wid >> 2;        // 0..1 -> rows wm*64
    const int wn   = wid & 3;         // 0..3 -> cols wn*64
    const int mt = blockIdx.x & 7;    // consecutive bx share an N-tile (W L2 reuse)
    const int nt = blockIdx.x >> 3;
    const int m0 = mt * MT, n0 = nt * NT;

    float acc[4][8][4];
#pragma unroll
    for (int f = 0; f < 4; f++)
#pragma unroll
        for (int bf = 0; bf < 8; bf++)
#pragma unroll
            for (int k = 0; k < 4; k++) acc[f][bf][k] = 0.f;

    auto stage_load = [&](int s, int kt) {
        uint32_t sA = sbase + (uint32_t)(s * STG_H) * 2u;
        uint32_t sB = sA + (uint32_t)A_ST * 2u;
        const __half* ga = gA + (size_t)m0 * D_DIM + kt * KC;
        const __half* gb = gB + (size_t)n0 * D_DIM + kt * KC;
#pragma unroll
        for (int i = 0; i < 4; i++) {                 // A: 1024 chunks
            int ch = tid + i * 256, row = ch >> 3, cc = ch & 7;
            CP_ASYNC16(sA + (uint32_t)(row * PITCH + cc * 8) * 2u,
                       ga + (size_t)row * D_DIM + cc * 8);
        }
#pragma unroll
        for (int i = 0; i < 8; i++) {                 // B: 2048 chunks
            int ch = tid + i * 256, row = ch >> 3, cc = ch & 7;
            CP_ASYNC16(sB + (uint32_t)(row * PITCH + cc * 8) * 2u,
                       gb + (size_t)row * D_DIM + cc * 8);
        }
    };

#pragma unroll
    for (int s = 0; s < 3; s++) { stage_load(s, s); CP_COMMIT(); }

    for (int it = 0; it < N_ITER; it++) {
        const int s = it & (N_STAGES - 1);
        CP_WAIT2();
        __syncthreads();
        if (it + 3 < N_ITER) stage_load((it + 3) & (N_STAGES - 1), it + 3);
        CP_COMMIT();

        const __half* sA = smem + s * STG_H;
        const __half* sB = sA + A_ST;
        const int rA = wm * 64 + (lane >> 2);
        const int nB = wn * 64 + (lane >> 2);
        const int kt = (lane & 3) * 2;
#pragma unroll
        for (int kk = 0; kk < 4; kk++) {
            const int k0 = kk * 16 + kt;
            uint32_t a[4][4];
#pragma unroll
            for (int f = 0; f < 4; f++) {
                const __half* ar = sA + (rA + f * 16) * PITCH + k0;
                a[f][0] = *(const uint32_t*)(ar);
                a[f][1] = *(const uint32_t*)(ar + 8 * PITCH);
                a[f][2] = *(const uint32_t*)(ar + 8);
                a[f][3] = *(const uint32_t*)(ar + 8 * PITCH + 8);
            }
#pragma unroll
            for (int bf = 0; bf < 8; bf++) {
                const __half* br = sB + (nB + bf * 8) * PITCH + k0;
                uint32_t b[2];
                b[0] = *(const uint32_t*)(br);
                b[1] = *(const uint32_t*)(br + 8);
#pragma unroll
                for (int f = 0; f < 4; f++) mma_f16(acc[f][bf], a[f], b);
            }
        }
    }

    // ---- epilogue: bias + tanh, float2 stores ----
#pragma unroll
    for (int f = 0; f < 4; f++) {
        const int r0 = m0 + wm * 64 + f * 16 + (lane >> 2);
#pragma unroll
        for (int bf = 0; bf < 8; bf++) {
            const int cb = n0 + wn * 64 + bf * 8 + 2 * (lane & 3);
            const float b0 = __ldg(bias + cb), b1 = __ldg(bias + cb + 1);
            float2 v0 = {tanhf(acc[f][bf][0] + b0), tanhf(acc[f][bf][1] + b1)};
            float2 v1 = {tanhf(acc[f][bf][2] + b0), tanhf(acc[f][bf][3] + b1)};
            *(float2*)(out + (size_t)r0 * U_DIM + cb) = v0;
            *(float2*)(out + (size_t)(r0 + 8) * U_DIM + cb) = v1;
        }
    }
}

// ---------------------------------------------------------------- host side
extern "C" void kernel_launch(void* const* d_in, const int* in_sizes, int n_in,
                              void* d_out, int out_size) {
    const float* x    = (const float*)d_in[0];
    const float* kv   = (const float*)d_in[1];
    const float* bias = (const float*)d_in[2];
    const int*   ind  = (const int*)d_in[3];
    float* out = (float*)d_out;
    int nnz = in_sizes[1];

    void* wptr = nullptr;
    void* xptr = nullptr;
    cudaGetSymbolAddress(&wptr, g_W);
    cudaGetSymbolAddress(&xptr, g_X);

    cudaFuncSetAttribute(sparse_gemm_kernel,
                         cudaFuncAttributeMaxDynamicSharedMemorySize, SMEM_DYN);

    // Fused prep: zero W (4M uint4) + convert x (2M float4) in one launch.
    int total = NW4 + NX4;
    prep_kernel<<<(total + 255) / 256, 256>>>((const float4*)x, (uint2*)xptr,
                                              (uint4*)wptr);

    scatter_kernel<<<(nnz + 255) / 256, 256>>>((const int2*)ind, kv, (__half*)wptr, nnz);

    sparse_gemm_kernel<<<(B_ROWS / MT) * (U_DIM / NT), 256, SMEM_DYN>>>(
        (const __half*)xptr, (const __half*)wptr, bias, out);
}